// round 11
// baseline (speedup 1.0000x reference)
#include <cuda_runtime.h>
#include <cuda_fp16.h>
#include <cstdint>
#include <cstddef>

// scratch (device globals): half2 packed as uint32_t
__device__ uint32_t g_h[16 * 256 * 64];    // [bh][l][x/2]
__device__ uint32_t g_v[16 * 256 * 64];    // [bh][k][y/2]
__device__ uint32_t g_Wt[512 * 128 * 64];  // [h*128+d][ks(8)][y(128)][8 words]

__device__ __forceinline__ uint32_t pack2(float lo, float hi) {
    __half2 p = __floats2half2_rn(lo, hi);
    return *(uint32_t*)&p;
}
__device__ __forceinline__ void mma16(float* c, const uint32_t* a, const uint32_t* b) {
    asm volatile(
        "mma.sync.aligned.m16n8k16.row.col.f32.f16.f16.f32 "
        "{%0,%1,%2,%3},{%4,%5,%6,%7},{%8,%9},{%0,%1,%2,%3};"
        : "+f"(c[0]), "+f"(c[1]), "+f"(c[2]), "+f"(c[3])
        : "r"(a[0]), "r"(a[1]), "r"(a[2]), "r"(a[3]), "r"(b[0]), "r"(b[1]));
}
__device__ __forceinline__ void ldsm4(uint32_t* r, uint32_t addr) {
    asm volatile("ldmatrix.sync.aligned.m8n8.x4.shared.b16 {%0,%1,%2,%3},[%4];"
        : "=r"(r[0]), "=r"(r[1]), "=r"(r[2]), "=r"(r[3]) : "r"(addr));
}
__device__ __forceinline__ void ldsm2(uint32_t* r, uint32_t addr) {
    asm volatile("ldmatrix.sync.aligned.m8n8.x2.shared.b16 {%0,%1},[%2];"
        : "=r"(r[0]), "=r"(r[1]) : "r"(addr));
}
__device__ __forceinline__ void stsm4(uint32_t addr, uint32_t r0, uint32_t r1,
                                      uint32_t r2, uint32_t r3) {
    asm volatile("stmatrix.sync.aligned.m8n8.x4.shared.b16 [%0],{%1,%2,%3,%4};"
        :: "r"(addr), "r"(r0), "r"(r1), "r"(r2), "r"(r3));
}

// ---------------------------------------------------------------------------
// kprep: merged k0 (W->g_Wt, blocks 0..511) + k1 (MLPs, blocks 512..639).
// 256 threads. Dynamic smem 33280 B.
// ---------------------------------------------------------------------------
__global__ void __launch_bounds__(256) kprep(
    const float* __restrict__ W,
    const float* __restrict__ x,
    const float* __restrict__ Wh, const float* __restrict__ bh,
    const float* __restrict__ Wv, const float* __restrict__ bv)
{
    extern __shared__ char dyn[];
    const int bx = blockIdx.x;
    const int t = threadIdx.x;

    if (bx < 512) {
        // ---- k0: W [slice][x][y] fp32 -> g_Wt [slice][ks][y][frag] fp16 ----
        __half* s = (__half*)dyn;                 // 128*130 halfs
        const int slice = bx;
        const float* src = W + (size_t)slice * 16384;
#pragma unroll
        for (int i = 0; i < 16; i++) {
            int idx = (t + i * 256) * 4;
            int xc = idx >> 7, y = idx & 127;
            float4 v = *(const float4*)(src + idx);
            __half* d = s + xc * 130 + y;
            d[0] = __float2half_rn(v.x); d[1] = __float2half_rn(v.y);
            d[2] = __float2half_rn(v.z); d[3] = __float2half_rn(v.w);
        }
        __syncthreads();
        uint32_t* dst = g_Wt + (size_t)slice * 8192;
#pragma unroll
        for (int i = 0; i < 32; i++) {
            int widx = t + i * 256;
            int y = widx >> 6, xp = widx & 63;
            __half2 p = __halves2half2(s[(xp * 2) * 130 + y], s[(xp * 2 + 1) * 130 + y]);
            int ks = xp >> 3, rr = xp & 7;
            dst[ks * 1024 + y * 8 + (rr & 3) * 2 + (rr >> 2)] = *(uint32_t*)&p;
        }
        return;
    }

    // ---- k1: two 64x64 MLP GEMM tiles per block (sub = t>>7) ----
    const int sub = t >> 7;
    const int t1 = t & 127;
    const int tileid = (bx - 512) * 2 + sub;     // 0..255
    uint32_t* As = (uint32_t*)(dyn + sub * 6144);
    uint32_t* Bs = As + 768;

    const int m0 = (tileid & 15) * 64;
    const int n0g = (tileid >> 4) * 64;
    const bool is_h = (n0g < 512);
    const int n0 = is_h ? n0g : (n0g - 512);
    const float* Wp = is_h ? Wh : Wv;
    const float* bp = is_h ? bh : bv;
    uint32_t* outp = is_h ? g_h : g_v;

    const int lane = t1 & 31, w = t1 >> 5;
    const int wm = (w & 1) * 32, wn = (w >> 1) * 32;
    const int gid = lane >> 2, tig = lane & 3;
    const int lr = t1 >> 1, lcw = (t1 & 1) * 4;

    float acc[2][4][4];
#pragma unroll
    for (int i = 0; i < 2; i++)
#pragma unroll
        for (int j = 0; j < 4; j++)
#pragma unroll
            for (int r = 0; r < 4; r++) acc[i][j][r] = 0.f;

    for (int kc = 0; kc < 1024; kc += 16) {
        __syncthreads();
        float4 a0 = *(const float4*)(x + (size_t)(m0 + lr) * 1024 + kc + lcw * 2);
        float4 a1 = *(const float4*)(x + (size_t)(m0 + lr) * 1024 + kc + lcw * 2 + 4);
        float4 b0 = *(const float4*)(Wp + (size_t)(n0 + lr) * 1024 + kc + lcw * 2);
        float4 b1 = *(const float4*)(Wp + (size_t)(n0 + lr) * 1024 + kc + lcw * 2 + 4);
        uint32_t* ap = As + lr * 12 + lcw;
        ap[0] = pack2(a0.x, a0.y); ap[1] = pack2(a0.z, a0.w);
        ap[2] = pack2(a1.x, a1.y); ap[3] = pack2(a1.z, a1.w);
        uint32_t* bpp = Bs + lr * 12 + lcw;
        bpp[0] = pack2(b0.x, b0.y); bpp[1] = pack2(b0.z, b0.w);
        bpp[2] = pack2(b1.x, b1.y); bpp[3] = pack2(b1.z, b1.w);
        __syncthreads();

        uint32_t a[2][4], bf[4][2];
#pragma unroll
        for (int mt = 0; mt < 2; mt++) {
            int r = wm + mt * 16 + gid;
            a[mt][0] = As[r * 12 + tig];
            a[mt][1] = As[(r + 8) * 12 + tig];
            a[mt][2] = As[r * 12 + tig + 4];
            a[mt][3] = As[(r + 8) * 12 + tig + 4];
        }
#pragma unroll
        for (int nt = 0; nt < 4; nt++) {
            int c = wn + nt * 8 + gid;
            bf[nt][0] = Bs[c * 12 + tig];
            bf[nt][1] = Bs[c * 12 + tig + 4];
        }
#pragma unroll
        for (int mt = 0; mt < 2; mt++)
#pragma unroll
            for (int nt = 0; nt < 4; nt++)
                mma16(acc[mt][nt], a[mt], bf[nt]);
    }

#pragma unroll
    for (int mt = 0; mt < 2; mt++)
#pragma unroll
        for (int nt = 0; nt < 4; nt++)
#pragma unroll
            for (int half_row = 0; half_row < 2; half_row++) {
                int m = m0 + wm + mt * 16 + gid + half_row * 8;
                int nl = wn + nt * 8 + tig * 2;
                float v0 = acc[mt][nt][half_row * 2] + bp[n0 + nl];
                float v1 = acc[mt][nt][half_row * 2 + 1] + bp[n0 + nl + 1];
                v0 = (v0 > 0.f) ? v0 : 0.01f * v0;
                v1 = (v1 > 0.f) ? v1 : 0.01f * v1;
                int o = n0 + nl, head = o >> 7, dim = o & 127;
                int b = m >> 8, l = m & 255;
                outp[((size_t)(b * 4 + head) * 256 + l) * 64 + (dim >> 1)] =
                    pack2(v0, v1);
            }
}

// ---------------------------------------------------------------------------
// k2: biaffine, fp16 mma + ldmatrix/stmatrix, software-pipelined.
// 256 threads, ~113KB smem.
// ---------------------------------------------------------------------------
__global__ void __launch_bounds__(256, 1) k2(float* __restrict__ out)
{
    extern __shared__ uint32_t sm[];
    uint32_t* Ts = sm;                 // 256 rows * 68 = 17408 words
    uint32_t* hs = sm + 17408;         // 32 * 68 = 2176
    uint32_t* vs = sm + 17408 + 2176;  // 128 * 68 = 8704

    const int dg = blockIdx.x, lt = blockIdx.y, bhi = blockIdx.z;
    const int b = bhi >> 2, h = bhi & 3;
    const int t = threadIdx.x, lane = t & 31, w = t >> 5;
    const int gid = lane >> 2, tig = lane & 3;
    const int l0 = lt * 32;

    const uint32_t ts_base = (uint32_t)__cvta_generic_to_shared(Ts);
    const uint32_t hs_base = (uint32_t)__cvta_generic_to_shared(hs);
    const uint32_t vs_base = (uint32_t)__cvta_generic_to_shared(vs);

    const int tile = lane >> 3, lrow = lane & 7;

    // load h tile [32 l][64 words]
    {
        const uint32_t* hp = g_h + ((size_t)bhi * 256 + l0) * 64;
#pragma unroll
        for (int i = 0; i < 2; i++) {
            int idx = t * 4 + i * 1024;
            int r = idx >> 6, c = idx & 63;
            *(uint4*)(hs + r * 68 + c) = *(const uint4*)(hp + idx);
        }
    }
    __syncthreads();

    // ---- stage 1: warp w owns d = w (pipelined W prefetch) ----
    {
        const uint32_t* Wd = g_Wt + (size_t)(h * 128 + dg * 8 + w) * 8192;
        uint32_t abase[2];
#pragma unroll
        for (int mt = 0; mt < 2; mt++) {
            int l = mt * 16 + (tile & 1) * 8 + lrow;
            abase[mt] = hs_base + l * 272 + (tile >> 1) * 16;
        }
#pragma unroll 1
        for (int nh = 0; nh < 2; nh++) {
            float acc[2][8][4];
#pragma unroll
            for (int i = 0; i < 2; i++)
#pragma unroll
                for (int j = 0; j < 8; j++)
#pragma unroll
                    for (int e = 0; e < 4; e++) acc[i][j][e] = 0.f;

            uint2 bw[8];
            uint32_t ac[2][4];
#pragma unroll
            for (int nt = 0; nt < 8; nt++)
                bw[nt] = *(const uint2*)(Wd + (nh * 64 + nt * 8 + gid) * 8 + tig * 2);
            ldsm4(ac[0], abase[0]);
            ldsm4(ac[1], abase[1]);

#pragma unroll
            for (int ks = 0; ks < 8; ks++) {
                uint2 bwn[8];
                uint32_t an[2][4];
                if (ks < 7) {
#pragma unroll
                    for (int nt = 0; nt < 8; nt++)
                        bwn[nt] = *(const uint2*)(Wd + (ks + 1) * 1024 +
                                                  (nh * 64 + nt * 8 + gid) * 8 + tig * 2);
                    ldsm4(an[0], abase[0] + (ks + 1) * 32);
                    ldsm4(an[1], abase[1] + (ks + 1) * 32);
                }
#pragma unroll
                for (int nt = 0; nt < 8; nt++) {
                    uint32_t bf[2] = {bw[nt].x, bw[nt].y};
                    mma16(acc[0][nt], ac[0], bf);
                    mma16(acc[1][nt], ac[1], bf);
                }
                if (ks < 7) {
#pragma unroll
                    for (int nt = 0; nt < 8; nt++) bw[nt] = bwn[nt];
#pragma unroll
                    for (int mt = 0; mt < 2; mt++)
#pragma unroll
                        for (int e = 0; e < 4; e++) ac[mt][e] = an[mt][e];
                }
            }
            // scatter to Ts via stmatrix
#pragma unroll
            for (int mt = 0; mt < 2; mt++) {
                int l = mt * 16 + (tile & 1) * 8 + lrow;
                uint32_t rowb = ts_base + (l * 8 + w) * 272;
#pragma unroll
                for (int ntp = 0; ntp < 4; ntp++) {
                    int ntA = ntp * 2;
                    int cw = (nh * 32 + (ntA + (tile >> 1)) * 4) ^ (lrow << 2);
                    stsm4(rowb + cw * 4,
                          pack2(acc[mt][ntA][0],     acc[mt][ntA][1]),
                          pack2(acc[mt][ntA][2],     acc[mt][ntA][3]),
                          pack2(acc[mt][ntA + 1][0], acc[mt][ntA + 1][1]),
                          pack2(acc[mt][ntA + 1][2], acc[mt][ntA + 1][3]));
                }
            }
        }
    }

    // ---- stage 2: 2 k-half passes; warp grid 4m x 2n; pipelined LDSM ----
    const int wm = (w & 3) * 64, wn = (w >> 2) * 64;
    uint32_t a_base[4], a_q[4];
#pragma unroll
    for (int mt = 0; mt < 4; mt++) {
        int m = wm + mt * 16 + (tile & 1) * 8 + lrow;
        int kxb = (((m >> 3) & 7) << 2) * 4;
        a_base[mt] = ts_base + m * 272;
        a_q[mt] = ((tile >> 1) * 16) ^ kxb;
    }
    const int bl = lane & 15;
    const int b_tile = bl >> 3, b_row = bl & 7;

#pragma unroll 1
    for (int khalf = 0; khalf < 2; khalf++) {
        __syncthreads();
        {
            const uint32_t* vp = g_v + ((size_t)bhi * 256 + khalf * 128) * 64;
#pragma unroll
            for (int i = 0; i < 8; i++) {
                int idx = t * 4 + i * 1024;
                int r = idx >> 6, c = idx & 63;
                *(uint4*)(vs + r * 68 + c) = *(const uint4*)(vp + idx);
            }
        }
        __syncthreads();

#pragma unroll 1
        for (int nq = 0; nq < 2; nq++) {
            float acc[4][4][4];
#pragma unroll
            for (int i = 0; i < 4; i++)
#pragma unroll
                for (int j = 0; j < 4; j++)
#pragma unroll
                    for (int e = 0; e < 4; e++) acc[i][j][e] = 0.f;

            uint32_t A[4][4], B[4][2];
#pragma unroll
            for (int mt = 0; mt < 4; mt++)
                ldsm4(A[mt], a_base[mt] + (0u ^ a_q[mt]));
#pragma unroll
            for (int nt = 0; nt < 4; nt++) {
                int nn = wn + nq * 32 + nt * 8 + b_row;
                ldsm2(B[nt], vs_base + nn * 272 + b_tile * 16);
            }

#pragma unroll
            for (int ks = 0; ks < 8; ks++) {
                uint32_t An[4][4], Bn[4][2];
                if (ks < 7) {
#pragma unroll
                    for (int mt = 0; mt < 4; mt++)
                        ldsm4(An[mt], a_base[mt] + (((uint32_t)((ks + 1) * 32)) ^ a_q[mt]));
#pragma unroll
                    for (int nt = 0; nt < 4; nt++) {
                        int nn = wn + nq * 32 + nt * 8 + b_row;
                        ldsm2(Bn[nt], vs_base + nn * 272 + (ks + 1) * 32 + b_tile * 16);
                    }
                }
#pragma unroll
                for (int nt = 0; nt < 4; nt++)
#pragma unroll
                    for (int mt = 0; mt < 4; mt++)
                        mma16(acc[mt][nt], A[mt], B[nt]);
                if (ks < 7) {
#pragma unroll
                    for (int mt = 0; mt < 4; mt++)
#pragma unroll
                        for (int e = 0; e < 4; e++) A[mt][e] = An[mt][e];
#pragma unroll
                    for (int nt = 0; nt < 4; nt++) {
                        B[nt][0] = Bn[nt][0]; B[nt][1] = Bn[nt][1];
                    }
                }
            }
            // epilogue: out[b, l, k, h*128+d]
#pragma unroll
            for (int mt = 0; mt < 4; mt++)
#pragma unroll
                for (int nt = 0; nt < 4; nt++) {
                    int m = wm + mt * 16 + gid;
                    int k = khalf * 128 + wn + nq * 32 + nt * 8 + tig * 2;
                    int l = l0 + (m >> 3), d = dg * 8 + (m & 7);
                    size_t base = (((size_t)b * 256 + l) * 256 + k) * 512 + h * 128 + d;
                    out[base]       = acc[mt][nt][0];
                    out[base + 512] = acc[mt][nt][1];
                    int m2 = m + 8;
                    int l2 = l0 + (m2 >> 3);
                    size_t base2 = (((size_t)b * 256 + l2) * 256 + k) * 512 + h * 128 + d;
                    out[base2]       = acc[mt][nt][2];
                    out[base2 + 512] = acc[mt][nt][3];
                }
        }
    }
}

extern "C" void kernel_launch(void* const* d_in, const int* in_sizes, int n_in,
                              void* d_out, int out_size)
{
    const float* x  = (const float*)d_in[0];
    const float* Wh = (const float*)d_in[1];
    const float* bh = (const float*)d_in[2];
    const float* Wv = (const float*)d_in[3];
    const float* bv = (const float*)d_in[4];
    const float* W  = (const float*)d_in[5];
    float* out = (float*)d_out;

    static bool attr_set = false;
    if (!attr_set) {
        cudaFuncSetAttribute(k2, cudaFuncAttributeMaxDynamicSharedMemorySize, 113152);
        attr_set = true;
    }

    kprep<<<640, 256, 33280>>>(W, x, Wh, bh, Wv, bv);
    k2<<<dim3(16, 8, 16), 256, 113152>>>(out);
}

// round 12
// speedup vs baseline: 1.4784x; 1.4784x over previous
#include <cuda_runtime.h>
#include <cuda_fp16.h>
#include <cstdint>
#include <cstddef>

// scratch (device globals): half2 packed as uint32_t
__device__ uint32_t g_h[16 * 256 * 64];    // [bh][l][x/2]
__device__ uint32_t g_v[16 * 256 * 64];    // [bh][k][y/2]
__device__ uint32_t g_Wt[512 * 128 * 64];  // [h*128+d][ks(8)][y(128)][8 words]

__device__ __forceinline__ uint32_t pack2(float lo, float hi) {
    __half2 p = __floats2half2_rn(lo, hi);
    return *(uint32_t*)&p;
}
__device__ __forceinline__ void mma16(float* c, const uint32_t* a, const uint32_t* b) {
    asm volatile(
        "mma.sync.aligned.m16n8k16.row.col.f32.f16.f16.f32 "
        "{%0,%1,%2,%3},{%4,%5,%6,%7},{%8,%9},{%0,%1,%2,%3};"
        : "+f"(c[0]), "+f"(c[1]), "+f"(c[2]), "+f"(c[3])
        : "r"(a[0]), "r"(a[1]), "r"(a[2]), "r"(a[3]), "r"(b[0]), "r"(b[1]));
}
__device__ __forceinline__ void ldsm4(uint32_t* r, uint32_t addr) {
    asm volatile("ldmatrix.sync.aligned.m8n8.x4.shared.b16 {%0,%1,%2,%3},[%4];"
        : "=r"(r[0]), "=r"(r[1]), "=r"(r[2]), "=r"(r[3]) : "r"(addr));
}
__device__ __forceinline__ void ldsm2(uint32_t* r, uint32_t addr) {
    asm volatile("ldmatrix.sync.aligned.m8n8.x2.shared.b16 {%0,%1},[%2];"
        : "=r"(r[0]), "=r"(r[1]) : "r"(addr));
}
__device__ __forceinline__ void stsm4(uint32_t addr, uint32_t r0, uint32_t r1,
                                      uint32_t r2, uint32_t r3) {
    asm volatile("stmatrix.sync.aligned.m8n8.x4.shared.b16 [%0],{%1,%2,%3,%4};"
        :: "r"(addr), "r"(r0), "r"(r1), "r"(r2), "r"(r3));
}

// ---------------------------------------------------------------------------
// kprep: merged k0 (W->g_Wt, blocks 0..511) + k1 (MLPs, blocks 512..639).
// 256 threads. Dynamic smem 33280 B.
// ---------------------------------------------------------------------------
__global__ void __launch_bounds__(256) kprep(
    const float* __restrict__ W,
    const float* __restrict__ x,
    const float* __restrict__ Wh, const float* __restrict__ bh,
    const float* __restrict__ Wv, const float* __restrict__ bv)
{
    extern __shared__ char dyn[];
    const int bx = blockIdx.x;
    const int t = threadIdx.x;

    if (bx < 512) {
        // ---- k0: W [slice][x][y] fp32 -> g_Wt [slice][ks][y][frag] fp16 ----
        __half* s = (__half*)dyn;                 // 128*130 halfs
        const int slice = bx;
        const float* src = W + (size_t)slice * 16384;
#pragma unroll
        for (int i = 0; i < 16; i++) {
            int idx = (t + i * 256) * 4;
            int xc = idx >> 7, y = idx & 127;
            float4 v = *(const float4*)(src + idx);
            __half* d = s + xc * 130 + y;
            d[0] = __float2half_rn(v.x); d[1] = __float2half_rn(v.y);
            d[2] = __float2half_rn(v.z); d[3] = __float2half_rn(v.w);
        }
        __syncthreads();
        uint32_t* dst = g_Wt + (size_t)slice * 8192;
#pragma unroll
        for (int i = 0; i < 32; i++) {
            int widx = t + i * 256;
            int y = widx >> 6, xp = widx & 63;
            __half2 p = __halves2half2(s[(xp * 2) * 130 + y], s[(xp * 2 + 1) * 130 + y]);
            int ks = xp >> 3, rr = xp & 7;
            dst[ks * 1024 + y * 8 + (rr & 3) * 2 + (rr >> 2)] = *(uint32_t*)&p;
        }
        return;
    }

    // ---- k1: two 64x64 MLP GEMM tiles per block (sub = t>>7) ----
    const int sub = t >> 7;
    const int t1 = t & 127;
    const int tileid = (bx - 512) * 2 + sub;     // 0..255
    uint32_t* As = (uint32_t*)(dyn + sub * 6144);
    uint32_t* Bs = As + 768;

    const int m0 = (tileid & 15) * 64;
    const int n0g = (tileid >> 4) * 64;
    const bool is_h = (n0g < 512);
    const int n0 = is_h ? n0g : (n0g - 512);
    const float* Wp = is_h ? Wh : Wv;
    const float* bp = is_h ? bh : bv;
    uint32_t* outp = is_h ? g_h : g_v;

    const int lane = t1 & 31, w = t1 >> 5;
    const int wm = (w & 1) * 32, wn = (w >> 1) * 32;
    const int gid = lane >> 2, tig = lane & 3;
    const int lr = t1 >> 1, lcw = (t1 & 1) * 4;

    float acc[2][4][4];
#pragma unroll
    for (int i = 0; i < 2; i++)
#pragma unroll
        for (int j = 0; j < 4; j++)
#pragma unroll
            for (int r = 0; r < 4; r++) acc[i][j][r] = 0.f;

    for (int kc = 0; kc < 1024; kc += 16) {
        __syncthreads();
        float4 a0 = *(const float4*)(x + (size_t)(m0 + lr) * 1024 + kc + lcw * 2);
        float4 a1 = *(const float4*)(x + (size_t)(m0 + lr) * 1024 + kc + lcw * 2 + 4);
        float4 b0 = *(const float4*)(Wp + (size_t)(n0 + lr) * 1024 + kc + lcw * 2);
        float4 b1 = *(const float4*)(Wp + (size_t)(n0 + lr) * 1024 + kc + lcw * 2 + 4);
        uint32_t* ap = As + lr * 12 + lcw;
        ap[0] = pack2(a0.x, a0.y); ap[1] = pack2(a0.z, a0.w);
        ap[2] = pack2(a1.x, a1.y); ap[3] = pack2(a1.z, a1.w);
        uint32_t* bpp = Bs + lr * 12 + lcw;
        bpp[0] = pack2(b0.x, b0.y); bpp[1] = pack2(b0.z, b0.w);
        bpp[2] = pack2(b1.x, b1.y); bpp[3] = pack2(b1.z, b1.w);
        __syncthreads();

        uint32_t a[2][4], bf[4][2];
#pragma unroll
        for (int mt = 0; mt < 2; mt++) {
            int r = wm + mt * 16 + gid;
            a[mt][0] = As[r * 12 + tig];
            a[mt][1] = As[(r + 8) * 12 + tig];
            a[mt][2] = As[r * 12 + tig + 4];
            a[mt][3] = As[(r + 8) * 12 + tig + 4];
        }
#pragma unroll
        for (int nt = 0; nt < 4; nt++) {
            int c = wn + nt * 8 + gid;
            bf[nt][0] = Bs[c * 12 + tig];
            bf[nt][1] = Bs[c * 12 + tig + 4];
        }
#pragma unroll
        for (int mt = 0; mt < 2; mt++)
#pragma unroll
            for (int nt = 0; nt < 4; nt++)
                mma16(acc[mt][nt], a[mt], bf[nt]);
    }

#pragma unroll
    for (int mt = 0; mt < 2; mt++)
#pragma unroll
        for (int nt = 0; nt < 4; nt++)
#pragma unroll
            for (int half_row = 0; half_row < 2; half_row++) {
                int m = m0 + wm + mt * 16 + gid + half_row * 8;
                int nl = wn + nt * 8 + tig * 2;
                float v0 = acc[mt][nt][half_row * 2] + bp[n0 + nl];
                float v1 = acc[mt][nt][half_row * 2 + 1] + bp[n0 + nl + 1];
                v0 = (v0 > 0.f) ? v0 : 0.01f * v0;
                v1 = (v1 > 0.f) ? v1 : 0.01f * v1;
                int o = n0 + nl, head = o >> 7, dim = o & 127;
                int b = m >> 8, l = m & 255;
                outp[((size_t)(b * 4 + head) * 256 + l) * 64 + (dim >> 1)] =
                    pack2(v0, v1);
            }
}

// ---------------------------------------------------------------------------
// k2: biaffine, fp16 mma + ldmatrix/stmatrix (R10 structure — ptxas-scheduled).
// 256 threads, ~113KB smem.
// ---------------------------------------------------------------------------
__global__ void __launch_bounds__(256, 1) k2(float* __restrict__ out)
{
    extern __shared__ uint32_t sm[];
    uint32_t* Ts = sm;                 // 256 rows * 68 = 17408 words
    uint32_t* hs = sm + 17408;         // 32 * 68 = 2176
    uint32_t* vs = sm + 17408 + 2176;  // 128 * 68 = 8704

    const int dg = blockIdx.x, lt = blockIdx.y, bhi = blockIdx.z;
    const int b = bhi >> 2, h = bhi & 3;
    const int t = threadIdx.x, lane = t & 31, w = t >> 5;
    const int gid = lane >> 2, tig = lane & 3;
    const int l0 = lt * 32;

    const uint32_t ts_base = (uint32_t)__cvta_generic_to_shared(Ts);
    const uint32_t hs_base = (uint32_t)__cvta_generic_to_shared(hs);
    const uint32_t vs_base = (uint32_t)__cvta_generic_to_shared(vs);

    const int tile = lane >> 3, lrow = lane & 7;   // ldmatrix lane decode

    // load h tile [32 l][64 words]
    {
        const uint32_t* hp = g_h + ((size_t)bhi * 256 + l0) * 64;
#pragma unroll
        for (int i = 0; i < 2; i++) {
            int idx = t * 4 + i * 1024;
            int r = idx >> 6, c = idx & 63;
            *(uint4*)(hs + r * 68 + c) = *(const uint4*)(hp + idx);
        }
    }
    __syncthreads();

    // ---- stage 1: warp w owns d = w ----
    {
        const uint32_t* Wd = g_Wt + (size_t)(h * 128 + dg * 8 + w) * 8192;
        uint32_t abase[2];
#pragma unroll
        for (int mt = 0; mt < 2; mt++) {
            int l = mt * 16 + (tile & 1) * 8 + lrow;
            abase[mt] = hs_base + l * 272 + (tile >> 1) * 16;
        }
#pragma unroll 1
        for (int nh = 0; nh < 2; nh++) {
            float acc[2][8][4];
#pragma unroll
            for (int i = 0; i < 2; i++)
#pragma unroll
                for (int j = 0; j < 8; j++)
#pragma unroll
                    for (int e = 0; e < 4; e++) acc[i][j][e] = 0.f;
#pragma unroll 2
            for (int ks = 0; ks < 8; ks++) {
                uint32_t a[2][4];
                ldsm4(a[0], abase[0] + ks * 32);
                ldsm4(a[1], abase[1] + ks * 32);
#pragma unroll
                for (int nt = 0; nt < 8; nt++) {
                    int y = nh * 64 + nt * 8 + gid;
                    uint2 bw = *(const uint2*)(Wd + ks * 1024 + y * 8 + tig * 2);
                    uint32_t bf[2] = {bw.x, bw.y};
#pragma unroll
                    for (int mt = 0; mt < 2; mt++) mma16(acc[mt][nt], a[mt], bf);
                }
            }
            // scatter to Ts via stmatrix
#pragma unroll
            for (int mt = 0; mt < 2; mt++) {
                int l = mt * 16 + (tile & 1) * 8 + lrow;
                uint32_t rowb = ts_base + (l * 8 + w) * 272;
#pragma unroll
                for (int ntp = 0; ntp < 4; ntp++) {
                    int ntA = ntp * 2;
                    int cw = (nh * 32 + (ntA + (tile >> 1)) * 4) ^ (lrow << 2);
                    stsm4(rowb + cw * 4,
                          pack2(acc[mt][ntA][0],     acc[mt][ntA][1]),
                          pack2(acc[mt][ntA][2],     acc[mt][ntA][3]),
                          pack2(acc[mt][ntA + 1][0], acc[mt][ntA + 1][1]),
                          pack2(acc[mt][ntA + 1][2], acc[mt][ntA + 1][3]));
                }
            }
        }
    }

    // ---- stage 2: 2 k-half passes; warp grid 4m x 2n (64x64), n split in 2 ----
    const int wm = (w & 3) * 64, wn = (w >> 2) * 64;
    uint32_t a_base[4], a_q[4];
#pragma unroll
    for (int mt = 0; mt < 4; mt++) {
        int m = wm + mt * 16 + (tile & 1) * 8 + lrow;
        int kxb = (((m >> 3) & 7) << 2) * 4;           // swizzle, bytes
        a_base[mt] = ts_base + m * 272;
        a_q[mt] = ((tile >> 1) * 16) ^ kxb;
    }
    const int bl = lane & 15;
    const int b_tile = bl >> 3, b_row = bl & 7;

#pragma unroll 1
    for (int khalf = 0; khalf < 2; khalf++) {
        __syncthreads();  // Ts ready / prior vs reads done
        {
            const uint32_t* vp = g_v + ((size_t)bhi * 256 + khalf * 128) * 64;
#pragma unroll
            for (int i = 0; i < 8; i++) {
                int idx = t * 4 + i * 1024;
                int r = idx >> 6, c = idx & 63;
                *(uint4*)(vs + r * 68 + c) = *(const uint4*)(vp + idx);
            }
        }
        __syncthreads();

#pragma unroll 1
        for (int nq = 0; nq < 2; nq++) {
            float acc[4][4][4];
#pragma unroll
            for (int i = 0; i < 4; i++)
#pragma unroll
                for (int j = 0; j < 4; j++)
#pragma unroll
                    for (int e = 0; e < 4; e++) acc[i][j][e] = 0.f;
#pragma unroll 2
            for (int ks = 0; ks < 8; ks++) {
                uint32_t a[4][4];
#pragma unroll
                for (int mt = 0; mt < 4; mt++)
                    ldsm4(a[mt], a_base[mt] + ((uint32_t)(ks * 32) ^ a_q[mt]));
#pragma unroll
                for (int nt = 0; nt < 4; nt++) {
                    int nn = wn + nq * 32 + nt * 8 + b_row;
                    uint32_t bf[2];
                    ldsm2(bf, vs_base + nn * 272 + ks * 32 + b_tile * 16);
#pragma unroll
                    for (int mt = 0; mt < 4; mt++) mma16(acc[mt][nt], a[mt], bf);
                }
            }
            // epilogue: out[b, l, k, h*128+d]
#pragma unroll
            for (int mt = 0; mt < 4; mt++)
#pragma unroll
                for (int nt = 0; nt < 4; nt++) {
                    int m = wm + mt * 16 + gid;
                    int k = khalf * 128 + wn + nq * 32 + nt * 8 + tig * 2;
                    int l = l0 + (m >> 3), d = dg * 8 + (m & 7);
                    size_t base = (((size_t)b * 256 + l) * 256 + k) * 512 + h * 128 + d;
                    out[base]       = acc[mt][nt][0];
                    out[base + 512] = acc[mt][nt][1];
                    int m2 = m + 8;
                    int l2 = l0 + (m2 >> 3);
                    size_t base2 = (((size_t)b * 256 + l2) * 256 + k) * 512 + h * 128 + d;
                    out[base2]       = acc[mt][nt][2];
                    out[base2 + 512] = acc[mt][nt][3];
                }
        }
    }
}

extern "C" void kernel_launch(void* const* d_in, const int* in_sizes, int n_in,
                              void* d_out, int out_size)
{
    const float* x  = (const float*)d_in[0];
    const float* Wh = (const float*)d_in[1];
    const float* bh = (const float*)d_in[2];
    const float* Wv = (const float*)d_in[3];
    const float* bv = (const float*)d_in[4];
    const float* W  = (const float*)d_in[5];
    float* out = (float*)d_out;

    static bool attr_set = false;
    if (!attr_set) {
        cudaFuncSetAttribute(k2, cudaFuncAttributeMaxDynamicSharedMemorySize, 113152);
        attr_set = true;
    }

    kprep<<<640, 256, 33280>>>(W, x, Wh, bh, Wv, bv);
    k2<<<dim3(16, 8, 16), 256, 113152>>>(out);
}

// round 13
// speedup vs baseline: 1.6600x; 1.1228x over previous
#include <cuda_runtime.h>
#include <cuda_fp16.h>
#include <cstdint>
#include <cstddef>

// scratch (device globals): half2 packed as uint32_t
__device__ uint32_t g_h[16 * 256 * 64];    // [bh][l][x/2]
__device__ uint32_t g_v[16 * 256 * 64];    // [bh][k][y/2]
__device__ uint32_t g_Wt[512 * 128 * 64];  // [h*128+d][ks(8)][y(128)][8 words]

__device__ __forceinline__ uint32_t pack2(float lo, float hi) {
    __half2 p = __floats2half2_rn(lo, hi);
    return *(uint32_t*)&p;
}
__device__ __forceinline__ void mma16(float* c, const uint32_t* a, const uint32_t* b) {
    asm volatile(
        "mma.sync.aligned.m16n8k16.row.col.f32.f16.f16.f32 "
        "{%0,%1,%2,%3},{%4,%5,%6,%7},{%8,%9},{%0,%1,%2,%3};"
        : "+f"(c[0]), "+f"(c[1]), "+f"(c[2]), "+f"(c[3])
        : "r"(a[0]), "r"(a[1]), "r"(a[2]), "r"(a[3]), "r"(b[0]), "r"(b[1]));
}
__device__ __forceinline__ void ldsm4(uint32_t* r, uint32_t addr) {
    asm volatile("ldmatrix.sync.aligned.m8n8.x4.shared.b16 {%0,%1,%2,%3},[%4];"
        : "=r"(r[0]), "=r"(r[1]), "=r"(r[2]), "=r"(r[3]) : "r"(addr));
}
__device__ __forceinline__ void ldsm2(uint32_t* r, uint32_t addr) {
    asm volatile("ldmatrix.sync.aligned.m8n8.x2.shared.b16 {%0,%1},[%2];"
        : "=r"(r[0]), "=r"(r[1]) : "r"(addr));
}
__device__ __forceinline__ void stsm4(uint32_t addr, uint32_t r0, uint32_t r1,
                                      uint32_t r2, uint32_t r3) {
    asm volatile("stmatrix.sync.aligned.m8n8.x4.shared.b16 [%0],{%1,%2,%3,%4};"
        :: "r"(addr), "r"(r0), "r"(r1), "r"(r2), "r"(r3));
}

// ---------------------------------------------------------------------------
// k0: W [slice][x][y] fp32 -> g_Wt [slice][ks][y][frag] fp16 (B-frag layout)
// ---------------------------------------------------------------------------
__global__ void __launch_bounds__(256) k0(const float* __restrict__ W) {
    __shared__ __half s[128 * 130];
    const int slice = blockIdx.x;                 // h*128+d
    const float* src = W + (size_t)slice * 16384;
    const int t = threadIdx.x;
#pragma unroll
    for (int i = 0; i < 16; i++) {
        int idx = (t + i * 256) * 4;
        int x = idx >> 7, y = idx & 127;
        float4 v = *(const float4*)(src + idx);
        __half* d = s + x * 130 + y;
        d[0] = __float2half_rn(v.x); d[1] = __float2half_rn(v.y);
        d[2] = __float2half_rn(v.z); d[3] = __float2half_rn(v.w);
    }
    __syncthreads();
    uint32_t* dst = g_Wt + (size_t)slice * 8192;
#pragma unroll
    for (int i = 0; i < 32; i++) {
        int widx = t + i * 256;
        int y = widx >> 6, xp = widx & 63;
        __half2 p = __halves2half2(s[(xp * 2) * 130 + y], s[(xp * 2 + 1) * 130 + y]);
        int ks = xp >> 3, rr = xp & 7;
        dst[ks * 1024 + y * 8 + (rr & 3) * 2 + (rr >> 2)] = *(uint32_t*)&p;
    }
}

// ---------------------------------------------------------------------------
// k1: fused MLP, fp16 mma m16n8k16. Tile 64x64, 128 threads (4 warps 2x2).
// ---------------------------------------------------------------------------
__global__ void __launch_bounds__(128) k1(
    const float* __restrict__ x,
    const float* __restrict__ Wh, const float* __restrict__ bh,
    const float* __restrict__ Wv, const float* __restrict__ bv)
{
    __shared__ uint32_t As[64 * 12];
    __shared__ uint32_t Bs[64 * 12];

    const int m0 = blockIdx.x * 64;
    const int n0g = blockIdx.y * 64;
    const bool is_h = (n0g < 512);
    const int n0 = is_h ? n0g : (n0g - 512);
    const float* Wp = is_h ? Wh : Wv;
    const float* bp = is_h ? bh : bv;
    uint32_t* outp = is_h ? g_h : g_v;

    const int t = threadIdx.x, lane = t & 31, w = t >> 5;
    const int wm = (w & 1) * 32, wn = (w >> 1) * 32;
    const int gid = lane >> 2, tig = lane & 3;
    const int lr = t >> 1, lcw = (t & 1) * 4;

    float acc[2][4][4];
#pragma unroll
    for (int i = 0; i < 2; i++)
#pragma unroll
        for (int j = 0; j < 4; j++)
#pragma unroll
            for (int r = 0; r < 4; r++) acc[i][j][r] = 0.f;

    for (int kc = 0; kc < 1024; kc += 16) {
        __syncthreads();
        float4 a0 = *(const float4*)(x + (size_t)(m0 + lr) * 1024 + kc + lcw * 2);
        float4 a1 = *(const float4*)(x + (size_t)(m0 + lr) * 1024 + kc + lcw * 2 + 4);
        float4 b0 = *(const float4*)(Wp + (size_t)(n0 + lr) * 1024 + kc + lcw * 2);
        float4 b1 = *(const float4*)(Wp + (size_t)(n0 + lr) * 1024 + kc + lcw * 2 + 4);
        uint32_t* ap = As + lr * 12 + lcw;
        ap[0] = pack2(a0.x, a0.y); ap[1] = pack2(a0.z, a0.w);
        ap[2] = pack2(a1.x, a1.y); ap[3] = pack2(a1.z, a1.w);
        uint32_t* bpp = Bs + lr * 12 + lcw;
        bpp[0] = pack2(b0.x, b0.y); bpp[1] = pack2(b0.z, b0.w);
        bpp[2] = pack2(b1.x, b1.y); bpp[3] = pack2(b1.z, b1.w);
        __syncthreads();

        uint32_t a[2][4], bf[4][2];
#pragma unroll
        for (int mt = 0; mt < 2; mt++) {
            int r = wm + mt * 16 + gid;
            a[mt][0] = As[r * 12 + tig];
            a[mt][1] = As[(r + 8) * 12 + tig];
            a[mt][2] = As[r * 12 + tig + 4];
            a[mt][3] = As[(r + 8) * 12 + tig + 4];
        }
#pragma unroll
        for (int nt = 0; nt < 4; nt++) {
            int c = wn + nt * 8 + gid;
            bf[nt][0] = Bs[c * 12 + tig];
            bf[nt][1] = Bs[c * 12 + tig + 4];
        }
#pragma unroll
        for (int mt = 0; mt < 2; mt++)
#pragma unroll
            for (int nt = 0; nt < 4; nt++)
                mma16(acc[mt][nt], a[mt], bf[nt]);
    }

#pragma unroll
    for (int mt = 0; mt < 2; mt++)
#pragma unroll
        for (int nt = 0; nt < 4; nt++)
#pragma unroll
            for (int half_row = 0; half_row < 2; half_row++) {
                int m = m0 + wm + mt * 16 + gid + half_row * 8;
                int nl = wn + nt * 8 + tig * 2;
                float v0 = acc[mt][nt][half_row * 2] + bp[n0 + nl];
                float v1 = acc[mt][nt][half_row * 2 + 1] + bp[n0 + nl + 1];
                v0 = (v0 > 0.f) ? v0 : 0.01f * v0;
                v1 = (v1 > 0.f) ? v1 : 0.01f * v1;
                int o = n0 + nl, head = o >> 7, dim = o & 127;
                int b = m >> 8, l = m & 255;
                outp[((size_t)(b * 4 + head) * 256 + l) * 64 + (dim >> 1)] =
                    pack2(v0, v1);
            }
}

// ---------------------------------------------------------------------------
// k2: biaffine, fp16 mma + ldmatrix/stmatrix. 256 threads, 113KB smem,
// __launch_bounds__(256, 2) -> 2 CTAs/SM (regs capped at 128).
// ---------------------------------------------------------------------------
__global__ void __launch_bounds__(256, 2) k2(float* __restrict__ out)
{
    extern __shared__ uint32_t sm[];
    uint32_t* Ts = sm;                 // 256 rows * 68 = 17408 words
    uint32_t* hs = sm + 17408;         // 32 * 68 = 2176
    uint32_t* vs = sm + 17408 + 2176;  // 128 * 68 = 8704

    const int dg = blockIdx.x, lt = blockIdx.y, bhi = blockIdx.z;
    const int b = bhi >> 2, h = bhi & 3;
    const int t = threadIdx.x, lane = t & 31, w = t >> 5;
    const int gid = lane >> 2, tig = lane & 3;
    const int l0 = lt * 32;

    const uint32_t ts_base = (uint32_t)__cvta_generic_to_shared(Ts);
    const uint32_t hs_base = (uint32_t)__cvta_generic_to_shared(hs);
    const uint32_t vs_base = (uint32_t)__cvta_generic_to_shared(vs);

    const int tile = lane >> 3, lrow = lane & 7;   // ldmatrix lane decode

    // load h tile [32 l][64 words]
    {
        const uint32_t* hp = g_h + ((size_t)bhi * 256 + l0) * 64;
#pragma unroll
        for (int i = 0; i < 2; i++) {
            int idx = t * 4 + i * 1024;
            int r = idx >> 6, c = idx & 63;
            *(uint4*)(hs + r * 68 + c) = *(const uint4*)(hp + idx);
        }
    }
    __syncthreads();

    // ---- stage 1: warp w owns d = w ----
    {
        const uint32_t* Wd = g_Wt + (size_t)(h * 128 + dg * 8 + w) * 8192;
        uint32_t abase[2];
#pragma unroll
        for (int mt = 0; mt < 2; mt++) {
            int l = mt * 16 + (tile & 1) * 8 + lrow;
            abase[mt] = hs_base + l * 272 + (tile >> 1) * 16;
        }
#pragma unroll 1
        for (int nh = 0; nh < 2; nh++) {
            float acc[2][8][4];
#pragma unroll
            for (int i = 0; i < 2; i++)
#pragma unroll
                for (int j = 0; j < 8; j++)
#pragma unroll
                    for (int e = 0; e < 4; e++) acc[i][j][e] = 0.f;
#pragma unroll 2
            for (int ks = 0; ks < 8; ks++) {
                uint32_t a[2][4];
                ldsm4(a[0], abase[0] + ks * 32);
                ldsm4(a[1], abase[1] + ks * 32);
#pragma unroll
                for (int nt = 0; nt < 8; nt++) {
                    int y = nh * 64 + nt * 8 + gid;
                    uint2 bw = *(const uint2*)(Wd + ks * 1024 + y * 8 + tig * 2);
                    uint32_t bf[2] = {bw.x, bw.y};
#pragma unroll
                    for (int mt = 0; mt < 2; mt++) mma16(acc[mt][nt], a[mt], bf);
                }
            }
            // scatter to Ts via stmatrix
#pragma unroll
            for (int mt = 0; mt < 2; mt++) {
                int l = mt * 16 + (tile & 1) * 8 + lrow;
                uint32_t rowb = ts_base + (l * 8 + w) * 272;
#pragma unroll
                for (int ntp = 0; ntp < 4; ntp++) {
                    int ntA = ntp * 2;
                    int cw = (nh * 32 + (ntA + (tile >> 1)) * 4) ^ (lrow << 2);
                    stsm4(rowb + cw * 4,
                          pack2(acc[mt][ntA][0],     acc[mt][ntA][1]),
                          pack2(acc[mt][ntA][2],     acc[mt][ntA][3]),
                          pack2(acc[mt][ntA + 1][0], acc[mt][ntA + 1][1]),
                          pack2(acc[mt][ntA + 1][2], acc[mt][ntA + 1][3]));
                }
            }
        }
    }

    // ---- stage 2: 2 k-half passes; warp grid 4m x 2n (64x64), n split in 2 ----
    const int wm = (w & 3) * 64, wn = (w >> 2) * 64;
    uint32_t a_base[4], a_q[4];
#pragma unroll
    for (int mt = 0; mt < 4; mt++) {
        int m = wm + mt * 16 + (tile & 1) * 8 + lrow;
        int kxb = (((m >> 3) & 7) << 2) * 4;           // swizzle, bytes
        a_base[mt] = ts_base + m * 272;
        a_q[mt] = ((tile >> 1) * 16) ^ kxb;
    }
    const int bl = lane & 15;
    const int b_tile = bl >> 3, b_row = bl & 7;

#pragma unroll 1
    for (int khalf = 0; khalf < 2; khalf++) {
        __syncthreads();  // Ts ready / prior vs reads done
        {
            const uint32_t* vp = g_v + ((size_t)bhi * 256 + khalf * 128) * 64;
#pragma unroll
            for (int i = 0; i < 8; i++) {
                int idx = t * 4 + i * 1024;
                int r = idx >> 6, c = idx & 63;
                *(uint4*)(vs + r * 68 + c) = *(const uint4*)(vp + idx);
            }
        }
        __syncthreads();

#pragma unroll 1
        for (int nq = 0; nq < 2; nq++) {
            float acc[4][4][4];
#pragma unroll
            for (int i = 0; i < 4; i++)
#pragma unroll
                for (int j = 0; j < 4; j++)
#pragma unroll
                    for (int e = 0; e < 4; e++) acc[i][j][e] = 0.f;
#pragma unroll 2
            for (int ks = 0; ks < 8; ks++) {
                uint32_t a[4][4];
#pragma unroll
                for (int mt = 0; mt < 4; mt++)
                    ldsm4(a[mt], a_base[mt] + ((uint32_t)(ks * 32) ^ a_q[mt]));
#pragma unroll
                for (int nt = 0; nt < 4; nt++) {
                    int nn = wn + nq * 32 + nt * 8 + b_row;
                    uint32_t bf[2];
                    ldsm2(bf, vs_base + nn * 272 + ks * 32 + b_tile * 16);
#pragma unroll
                    for (int mt = 0; mt < 4; mt++) mma16(acc[mt][nt], a[mt], bf);
                }
            }
            // epilogue: out[b, l, k, h*128+d]
#pragma unroll
            for (int mt = 0; mt < 4; mt++)
#pragma unroll
                for (int nt = 0; nt < 4; nt++) {
                    int m = wm + mt * 16 + gid;
                    int k = khalf * 128 + wn + nq * 32 + nt * 8 + tig * 2;
                    int l = l0 + (m >> 3), d = dg * 8 + (m & 7);
                    size_t base = (((size_t)b * 256 + l) * 256 + k) * 512 + h * 128 + d;
                    out[base]       = acc[mt][nt][0];
                    out[base + 512] = acc[mt][nt][1];
                    int m2 = m + 8;
                    int l2 = l0 + (m2 >> 3);
                    size_t base2 = (((size_t)b * 256 + l2) * 256 + k) * 512 + h * 128 + d;
                    out[base2]       = acc[mt][nt][2];
                    out[base2 + 512] = acc[mt][nt][3];
                }
        }
    }
}

extern "C" void kernel_launch(void* const* d_in, const int* in_sizes, int n_in,
                              void* d_out, int out_size)
{
    const float* x  = (const float*)d_in[0];
    const float* Wh = (const float*)d_in[1];
    const float* bh = (const float*)d_in[2];
    const float* Wv = (const float*)d_in[3];
    const float* bv = (const float*)d_in[4];
    const float* W  = (const float*)d_in[5];
    float* out = (float*)d_out;

    static bool attr_set = false;
    if (!attr_set) {
        cudaFuncSetAttribute(k2, cudaFuncAttributeMaxDynamicSharedMemorySize, 113152);
        attr_set = true;
    }

    k0<<<512, 256>>>(W);
    k1<<<dim3(16, 16), 128>>>(x, Wh, bh, Wv, bv);
    k2<<<dim3(16, 8, 16), 256, 113152>>>(out);
}